// round 15
// baseline (speedup 1.0000x reference)
#include <cuda_runtime.h>
#include <cuda_fp16.h>
#include <cstdint>
#include <math.h>

#define D_MODEL 512
#define SEQ     1024
#define BATCH   8
#define HEADS   8
#define FF      2048
#define TOKENS  (BATCH*SEQ)     /* 8192 */

// ---------------------------------------------------------------------------
// Scratch (static __device__ arrays; allocation-free per harness rules)
// ---------------------------------------------------------------------------
__device__ __half g_xh    [(size_t)TOKENS * D_MODEL];
__device__ __half g_wqkTh [(size_t)1024 * D_MODEL];            // [n=q|k][d]
__device__ __half g_vwh   [(size_t)HEADS * D_MODEL * D_MODEL]; // vw as half [h][d'][e]
__device__ __half g_lwTh  [(size_t)D_MODEL * HEADS * D_MODEL]; // [512][4096]
__device__ __half g_WTh   [(size_t)HEADS * D_MODEL * D_MODEL]; // W^T per head [h][d][d']
__device__ __half g_w1Th  [(size_t)FF * D_MODEL];              // [2048][512]
__device__ __half g_w2Th  [(size_t)D_MODEL * FF];              // [512][2048]
__device__ __half g_qkh   [(size_t)TOKENS * 1024];             // [token][q|k]
__device__ __half g_yT    [(size_t)BATCH * D_MODEL * (HEADS*SEQ)]; // [b][d][h*1024+t]
__device__ __half g_scoresh[(size_t)BATCH*HEADS * SEQ * SEQ];      // [b][h][s][t]
__device__ __half g_probs2 [(size_t)BATCH * SEQ * (HEADS*SEQ)];    // [b][s][h*1024+t]
__device__ float  g_tmp   [(size_t)TOKENS * D_MODEL];
__device__ float  g_h     [(size_t)TOKENS * D_MODEL];
__device__ __half g_hh    [(size_t)TOKENS * D_MODEL];
__device__ __half g_ff1h  [(size_t)TOKENS * FF];

// ---------------------------------------------------------------------------
// PTX helpers (sm_80-era: cp.async, ldmatrix, mma.sync — valid on plain sm_103)
// ---------------------------------------------------------------------------
__device__ __forceinline__ void cp16(uint32_t s, const void* g) {
    asm volatile("cp.async.cg.shared.global [%0], [%1], 16;"
                 :: "r"(s), "l"(__cvta_generic_to_global(g)));
}
#define CP_COMMIT() asm volatile("cp.async.commit_group;" ::: "memory")

__device__ __forceinline__ void ldsm4(uint32_t* r, uint32_t a) {
    asm volatile("ldmatrix.sync.aligned.m8n8.x4.shared.b16 {%0,%1,%2,%3}, [%4];"
                 : "=r"(r[0]), "=r"(r[1]), "=r"(r[2]), "=r"(r[3]) : "r"(a));
}
__device__ __forceinline__ void mma16816(float* d, const uint32_t* a, const uint32_t* b) {
    asm volatile("mma.sync.aligned.m16n8k16.row.col.f32.f16.f16.f32 "
                 "{%0,%1,%2,%3}, {%4,%5,%6,%7}, {%8,%9}, {%0,%1,%2,%3};"
                 : "+f"(d[0]), "+f"(d[1]), "+f"(d[2]), "+f"(d[3])
                 : "r"(a[0]), "r"(a[1]), "r"(a[2]), "r"(a[3]), "r"(b[0]), "r"(b[1]));
}

// ---------------------------------------------------------------------------
// fp16 mma.sync batched GEMM: C[M,N] = A[M,K] @ B[N,K]^T, K-major rows.
// CTA tile 256x128, K-chunk 64 halves, 3-stage cp.async (48KB/stage, 144KB),
// 256 threads = 8 warps in 4(m) x 2(n) grid, 64x64 per warp.
// B fragments loaded pairwise via ldmatrix.x4 (2 n-frags per instruction).
// ---------------------------------------------------------------------------
#define STAGES 3
#define A_BYTES 32768                /* 256 rows x 128B */
#define B_BYTES 16384                /* 128 rows x 128B */
#define STG     (A_BYTES + B_BYTES)  /* 48KB */
#define SMEM_TOTAL (STAGES * STG)

struct GemmP {
    const __half* A; const __half* B; float* C; __half* Ch; const float* bias;
    int K, lda, ldb, ldc;
    long aOut, aIn, bOut, bIn, cOut, cIn;
    int inner, relu;
};

__global__ __launch_bounds__(256) void hgemm(GemmP p) {
    extern __shared__ char smem[];
    const uint32_t sb = (uint32_t)__cvta_generic_to_shared(smem);
    const int tid = threadIdx.x, wid = tid >> 5, lane = tid & 31;
    const int wm = wid >> 1, wn = wid & 1;        // 4 x 2 warp grid

    const int bi = blockIdx.z, bo = bi / p.inner, bn = bi % p.inner;
    const __half* A = p.A + (long)bo * p.aOut + (long)bn * p.aIn
                          + (long)(blockIdx.y * 256) * p.lda;
    const __half* B = p.B + (long)bo * p.bOut + (long)bn * p.bIn
                          + (long)(blockIdx.x * 128) * p.ldb;

    const int nk = p.K >> 6;

    // stage layout: [A 256x128B | B 128x128B], rows XOR-swizzled (16B granules)
    auto load_stage = [&](int s, int kc) {
        const uint32_t sd = sb + s * STG;
        const __half* ga = A + kc * 64;
        const __half* gb = B + kc * 64;
        // A: 2048 granules, 8 per thread
#pragma unroll
        for (int i = 0; i < 8; i++) {
            int id = tid + i * 256;
            int row = id >> 3, c = id & 7;
            uint32_t sw = row * 128 + (uint32_t)((c ^ (row & 7)) << 4);
            cp16(sd + sw, ga + (long)row * p.lda + c * 8);
        }
        // B: 1024 granules, 4 per thread
#pragma unroll
        for (int i = 0; i < 4; i++) {
            int id = tid + i * 256;
            int row = id >> 3, c = id & 7;
            uint32_t sw = row * 128 + (uint32_t)((c ^ (row & 7)) << 4);
            cp16(sd + A_BYTES + sw, gb + (long)row * p.ldb + c * 8);
        }
    };

    for (int s = 0; s < STAGES; s++) {
        if (s < nk) load_stage(s, s);
        CP_COMMIT();
    }

    float acc[4][8][4];
#pragma unroll
    for (int i = 0; i < 4; i++)
#pragma unroll
        for (int j = 0; j < 8; j++)
#pragma unroll
            for (int r = 0; r < 4; r++) acc[i][j][r] = 0.f;

    int s = 0;
    for (int k = 0; k < nk; k++) {
        asm volatile("cp.async.wait_group %0;" :: "n"(STAGES - 1));
        __syncthreads();

        const uint32_t sa = sb + s * STG;
        const uint32_t sB = sa + A_BYTES;
#pragma unroll
        for (int ks = 0; ks < 4; ks++) {
            uint32_t af[4][4], bf[8][2];
#pragma unroll
            for (int mi = 0; mi < 4; mi++) {
                int row = wm * 64 + mi * 16 + (lane & 15);
                int ch = 2 * ks + (lane >> 4);
                ldsm4(af[mi], sa + row * 128 + ((ch ^ (row & 7)) << 4));
            }
            // B: one ldsm4 covers two n-fragments (ni, ni+1)
#pragma unroll
            for (int nc = 0; nc < 4; nc++) {
                int row = wn * 64 + (nc * 2 + ((lane >> 4) & 1)) * 8 + (lane & 7);
                int ch = 2 * ks + ((lane >> 3) & 1);
                uint32_t r4[4];
                ldsm4(r4, sB + row * 128 + ((ch ^ (row & 7)) << 4));
                bf[nc * 2][0] = r4[0]; bf[nc * 2][1] = r4[1];
                bf[nc * 2 + 1][0] = r4[2]; bf[nc * 2 + 1][1] = r4[3];
            }
#pragma unroll
            for (int mi = 0; mi < 4; mi++)
#pragma unroll
                for (int ni = 0; ni < 8; ni++)
                    mma16816(acc[mi][ni], af[mi], bf[ni]);
        }
        __syncthreads();
        if (k + STAGES < nk) load_stage(s, k + STAGES);
        CP_COMMIT();
        if (++s == STAGES) s = 0;
    }

    float* C = p.C ? p.C + (long)bo * p.cOut + (long)bn * p.cIn : nullptr;
    __half* Ch = p.Ch ? p.Ch + (long)bo * p.cOut + (long)bn * p.cIn : nullptr;
    const int g = lane >> 2, tc = (lane & 3) * 2;
#pragma unroll
    for (int mi = 0; mi < 4; mi++) {
        const int r0 = blockIdx.y * 256 + wm * 64 + mi * 16 + g;
#pragma unroll
        for (int ni = 0; ni < 8; ni++) {
            const int c = blockIdx.x * 128 + wn * 64 + ni * 8 + tc;
            float v00 = acc[mi][ni][0], v01 = acc[mi][ni][1];
            float v10 = acc[mi][ni][2], v11 = acc[mi][ni][3];
            if (p.bias) {
                const float b0 = p.bias[c], b1 = p.bias[c + 1];
                v00 += b0; v01 += b1; v10 += b0; v11 += b1;
            }
            if (p.relu) {
                v00 = fmaxf(v00, 0.f); v01 = fmaxf(v01, 0.f);
                v10 = fmaxf(v10, 0.f); v11 = fmaxf(v11, 0.f);
            }
            if (C) {
                *(float2*)(C + (long)r0 * p.ldc + c)       = make_float2(v00, v01);
                *(float2*)(C + (long)(r0 + 8) * p.ldc + c) = make_float2(v10, v11);
            }
            if (Ch) {
                *(__half2*)(Ch + (long)r0 * p.ldc + c)       = __floats2half2_rn(v00, v01);
                *(__half2*)(Ch + (long)(r0 + 8) * p.ldc + c) = __floats2half2_rn(v10, v11);
            }
        }
    }
}

// ---------------------------------------------------------------------------
// Packing / conversion kernels
// ---------------------------------------------------------------------------
__global__ void conv_half(const float* __restrict__ in, __half* __restrict__ out, int n) {
    int i = blockIdx.x * blockDim.x + threadIdx.x;
    if (i < n) out[i] = __float2half_rn(in[i]);
}

__global__ void pack_qk_h(const float* __restrict__ qw, const float* __restrict__ kw) {
    int idx = blockIdx.x * blockDim.x + threadIdx.x;   // 1024*512
    if (idx >= 1024 * 512) return;
    int n = idx >> 9, d = idx & 511;
    float v;
    if (n < 512) { int h = n >> 6, u = n & 63; v = qw[(h * 512 + d) * 64 + u]; }
    else { int nn = n - 512; int h = nn >> 6, u = nn & 63; v = kw[(h * 512 + d) * 64 + u]; }
    g_wqkTh[idx] = __float2half_rn(v);
}

// in[b][R][C] fp32 -> out[b][C][R] half
__global__ void transpose_h(const float* __restrict__ in, __half* __restrict__ out,
                            int R, int C, long inStride, long outStride) {
    __shared__ float t[32][33];
    const long b = blockIdx.z;
    const int r0 = blockIdx.y * 32, c0 = blockIdx.x * 32;
    const float* I = in + b * inStride;
    __half* O = out + b * outStride;
#pragma unroll
    for (int i = 0; i < 32; i += 8)
        t[threadIdx.y + i][threadIdx.x] = I[(long)(r0 + threadIdx.y + i) * C + c0 + threadIdx.x];
    __syncthreads();
#pragma unroll
    for (int i = 0; i < 32; i += 8)
        O[(long)(c0 + threadIdx.y + i) * R + r0 + threadIdx.x] =
            __float2half_rn(t[threadIdx.x][threadIdx.y + i]);
}

// ---------------------------------------------------------------------------
// Softmax: half scores [b][h][s][t] -> half probs2 [b][s][h*1024+t]
// ---------------------------------------------------------------------------
__device__ __forceinline__ float warp_max(float v) {
#pragma unroll
    for (int o = 16; o; o >>= 1) v = fmaxf(v, __shfl_xor_sync(0xffffffffu, v, o));
    return v;
}
__device__ __forceinline__ float warp_sum(float v) {
#pragma unroll
    for (int o = 16; o; o >>= 1) v += __shfl_xor_sync(0xffffffffu, v, o);
    return v;
}

__global__ __launch_bounds__(256) void softmax_k(const __half* __restrict__ sc,
                                                 __half* __restrict__ pout) {
    const float scale = 0.04419417382415922f;  // 1/sqrt(512)
    const int i = blockIdx.x;                  // b*8192 + h*1024 + s
    const int b = i >> 13, h = (i >> 10) & 7, srow = i & 1023;
    const __half* row = sc + (size_t)i * SEQ;
    __half* orow = pout + ((size_t)(b * 1024 + srow) * 8192) + h * 1024;
    const int t = threadIdx.x;
    __shared__ float red[8];
    float v[4];
    float mx = -1e30f;
#pragma unroll
    for (int j = 0; j < 4; j++) {
        v[j] = __half2float(row[t + j * 256]) * scale;
        mx = fmaxf(mx, v[j]);
    }
    mx = warp_max(mx);
    if ((t & 31) == 0) red[t >> 5] = mx;
    __syncthreads();
    mx = fmaxf(fmaxf(fmaxf(red[0], red[1]), fmaxf(red[2], red[3])),
               fmaxf(fmaxf(red[4], red[5]), fmaxf(red[6], red[7])));
    __syncthreads();
    float sum = 0.f;
#pragma unroll
    for (int j = 0; j < 4; j++) { v[j] = __expf(v[j] - mx); sum += v[j]; }
    sum = warp_sum(sum);
    if ((t & 31) == 0) red[t >> 5] = sum;
    __syncthreads();
    sum = red[0] + red[1] + red[2] + red[3] + red[4] + red[5] + red[6] + red[7];
    const float inv = 1.0f / sum;
#pragma unroll
    for (int j = 0; j < 4; j++) orow[t + j * 256] = __float2half_rn(v[j] * inv);
}

// ---------------------------------------------------------------------------
// out = LayerNorm(a + b), optional half copy
// ---------------------------------------------------------------------------
__global__ __launch_bounds__(256) void add_ln_k(const float* __restrict__ a,
                                                const float* __restrict__ b,
                                                const float* __restrict__ gamma,
                                                const float* __restrict__ beta,
                                                float* __restrict__ out,
                                                __half* __restrict__ out_h) {
    const size_t base = (size_t)blockIdx.x * D_MODEL;
    const int t = threadIdx.x;
    __shared__ float red[8];
    float s0 = a[base + t] + b[base + t];
    float s1 = a[base + t + 256] + b[base + t + 256];
    float sum = warp_sum(s0 + s1);
    if ((t & 31) == 0) red[t >> 5] = sum;
    __syncthreads();
    float mean = (red[0]+red[1]+red[2]+red[3]+red[4]+red[5]+red[6]+red[7]) * (1.0f / D_MODEL);
    __syncthreads();
    const float d0 = s0 - mean, d1 = s1 - mean;
    float sq = warp_sum(d0 * d0 + d1 * d1);
    if ((t & 31) == 0) red[t >> 5] = sq;
    __syncthreads();
    float var = (red[0]+red[1]+red[2]+red[3]+red[4]+red[5]+red[6]+red[7]) * (1.0f / D_MODEL);
    const float inv = rsqrtf(var + 1e-3f);
    float o0 = gamma[t]       * d0 * inv + beta[t];
    float o1 = gamma[t + 256] * d1 * inv + beta[t + 256];
    out[base + t] = o0;
    out[base + t + 256] = o1;
    if (out_h) {
        out_h[base + t] = __float2half_rn(o0);
        out_h[base + t + 256] = __float2half_rn(o1);
    }
}

// ---------------------------------------------------------------------------
// Host side
// ---------------------------------------------------------------------------
static void launch_hgemm(const __half* A, const __half* B, float* C, __half* Ch,
                         const float* bias, int M, int N, int K,
                         int lda, int ldb, int ldc,
                         long aOut, long aIn, long bOut, long bIn, long cOut, long cIn,
                         int nb, int inner, int relu) {
    GemmP p;
    p.A = A; p.B = B; p.C = C; p.Ch = Ch; p.bias = bias;
    p.K = K; p.lda = lda; p.ldb = ldb; p.ldc = ldc;
    p.aOut = aOut; p.aIn = aIn; p.bOut = bOut; p.bIn = bIn; p.cOut = cOut; p.cIn = cIn;
    p.inner = inner; p.relu = relu;
    dim3 grid(N / 128, M / 256, nb);
    hgemm<<<grid, 256, SMEM_TOTAL>>>(p);
}

extern "C" void kernel_launch(void* const* d_in, const int* in_sizes, int n_in,
                              void* d_out, int out_size) {
    const float* x      = (const float*)d_in[0];
    const float* qw     = (const float*)d_in[1];
    const float* kw     = (const float*)d_in[2];
    const float* vw     = (const float*)d_in[3];
    const float* lw     = (const float*)d_in[4];
    const float* gamma1 = (const float*)d_in[5];
    const float* beta1  = (const float*)d_in[6];
    const float* w1     = (const float*)d_in[7];
    const float* b1     = (const float*)d_in[8];
    const float* w2     = (const float*)d_in[9];
    const float* b2     = (const float*)d_in[10];
    const float* gamma2 = (const float*)d_in[11];
    const float* beta2  = (const float*)d_in[12];
    float* out = (float*)d_out;

    static int init = 0;
    if (!init) {
        cudaFuncSetAttribute(hgemm, cudaFuncAttributeMaxDynamicSharedMemorySize, SMEM_TOTAL);
        init = 1;
    }

    __half *xh, *wqkTh, *vwh, *lwTh, *WTh, *w1Th, *w2Th, *qkh, *yT, *scoresh, *probs2, *hh, *ff1h;
    float *tmp, *h;
    cudaGetSymbolAddress((void**)&xh,     g_xh);
    cudaGetSymbolAddress((void**)&wqkTh,  g_wqkTh);
    cudaGetSymbolAddress((void**)&vwh,    g_vwh);
    cudaGetSymbolAddress((void**)&lwTh,   g_lwTh);
    cudaGetSymbolAddress((void**)&WTh,    g_WTh);
    cudaGetSymbolAddress((void**)&w1Th,   g_w1Th);
    cudaGetSymbolAddress((void**)&w2Th,   g_w2Th);
    cudaGetSymbolAddress((void**)&qkh,    g_qkh);
    cudaGetSymbolAddress((void**)&yT,     g_yT);
    cudaGetSymbolAddress((void**)&scoresh,g_scoresh);
    cudaGetSymbolAddress((void**)&probs2, g_probs2);
    cudaGetSymbolAddress((void**)&tmp,    g_tmp);
    cudaGetSymbolAddress((void**)&h,      g_h);
    cudaGetSymbolAddress((void**)&hh,     g_hh);
    cudaGetSymbolAddress((void**)&ff1h,   g_ff1h);

    // --- pack to fp16 ---
    conv_half<<<(TOKENS * D_MODEL + 255) / 256, 256>>>(x, xh, TOKENS * D_MODEL);
    pack_qk_h<<<(1024 * 512 + 255) / 256, 256>>>(qw, kw);
    conv_half<<<(HEADS * 512 * 512 + 255) / 256, 256>>>(vw, vwh, HEADS * 512 * 512);
    { dim3 g(512/32, 4096/32, 1); transpose_h<<<g, dim3(32,8)>>>(lw, lwTh, 4096, 512, 0, 0); }
    { dim3 g(2048/32, 512/32, 1); transpose_h<<<g, dim3(32,8)>>>(w1, w1Th, 512, 2048, 0, 0); }
    { dim3 g(512/32, 2048/32, 1); transpose_h<<<g, dim3(32,8)>>>(w2, w2Th, 2048, 512, 0, 0); }

    // 0. WT_h[d][d'] = sum_e lwT[d][h*512+e] * vwh[h][d'][e]  (8 batches, 512^3)
    launch_hgemm(lwTh, vwh, nullptr, WTh, nullptr, 512, 512, 512,
                 4096, 512, 512,
                 0, 512, 0, 512L*512, 0, 512L*512,
                 8, 8, 0);

    // 1. qk = x @ [wq|wk]^T : [8192,1024], K=512
    launch_hgemm(xh, wqkTh, nullptr, qkh, nullptr, TOKENS, 1024, 512,
                 512, 512, 1024, 0, 0, 0, 0, 0, 0, 1, 1, 0);

    // 2. yT[b][d][h*1024+t] = WT_h @ x[b]^T : M=512(d),N=1024(t),K=512(d'), 64 batches
    launch_hgemm(WTh, xh, nullptr, yT, nullptr, 512, 1024, 512,
                 512, 512, 8192,
                 0, 512L*512, 1024L*512, 0, 512L*8192, 1024,
                 64, 8, 0);

    // 3. scores[b,h] = q @ k^T : M=N=1024, K=64 (half out)
    launch_hgemm(qkh, qkh + 512, nullptr, scoresh, nullptr, 1024, 1024, 64,
                 1024, 1024, 1024,
                 1024L*1024, 64, 1024L*1024, 64, 8L*1024*1024, 1024L*1024,
                 64, 8, 0);

    // 4. softmax -> probs2 [b][s][h*1024+t]
    softmax_k<<<BATCH * HEADS * SEQ, 256>>>(scoresh, probs2);

    // 5. mha[b] = probs2[b] @ yT[b]^T : M=1024,N=512,K=8192, 8 batches (fp32 out)
    launch_hgemm(probs2, yT, tmp, nullptr, nullptr, 1024, 512, 8192,
                 8192, 8192, 512,
                 1024L*8192, 0, 512L*8192, 0, 1024L*512, 0,
                 8, 1, 0);

    // 6. h = LN1(x + mha) (+ half copy)
    add_ln_k<<<TOKENS, 256>>>(x, tmp, gamma1, beta1, h, hh);

    // 7. ff1 = relu(h @ w1 + b1) : [8192,2048], K=512
    launch_hgemm(hh, w1Th, nullptr, ff1h, b1, TOKENS, 2048, 512,
                 512, 512, 2048, 0, 0, 0, 0, 0, 0, 1, 1, 1);

    // 8. ff2 = ff1 @ w2 + b2 : [8192,512], K=2048 (fp32 out)
    launch_hgemm(ff1h, w2Th, tmp, nullptr, b2, TOKENS, 512, 2048,
                 2048, 2048, 512, 0, 0, 0, 0, 0, 0, 1, 1, 0);

    // 9. out = LN2(h + ff2)
    add_ln_k<<<TOKENS, 256>>>(h, tmp, gamma2, beta2, out, nullptr);
}